// round 12
// baseline (speedup 1.0000x reference)
#include <cuda_runtime.h>
#include <math.h>

// CTC loss forward. 4 independent batch elements per CTA (groups of 128
// threads synced by NAMED barriers) so each SMSP interleaves 4 independent
// recursions and fills the exposed latency of each. Per group: two
// positions per thread in f32x2, block-floating-point alpha (linear
// mantissa + int exponent), 4-step fused pyramid, zero MUFU in the loop.
// B=64, T=1000, C=128 (blank=127), L=100, S=201.

#define Bc 64
#define Tc 1000
#define Cc 128
#define Lc 100
#define NG 4              // batch elements (groups) per CTA
#define GT 128            // threads per group
#define NTHREADS (NG*GT)
#define NPAIR 128
#define PADP 4
#define EDEAD (-(1 << 29))

#define EPSV (1e-7f)
#define LN2F 0.6931471805599453f

#define GBAR() asm volatile("bar.sync %0, %1;" :: "r"(g + 1), "n"(GT) : "memory")

__device__ __forceinline__ float lg2a(float x) {
    float y; asm("lg2.approx.f32 %0, %1;" : "=f"(y) : "f"(x)); return y;
}
__device__ __forceinline__ float2 add2(float2 a, float2 b) {
    float2 r;
    asm("{\n\t.reg .b64 A,B,D;\n\t"
        "mov.b64 A,{%2,%3};\n\tmov.b64 B,{%4,%5};\n\t"
        "add.rn.f32x2 D,A,B;\n\t"
        "mov.b64 {%0,%1},D;\n\t}"
        : "=f"(r.x), "=f"(r.y)
        : "f"(a.x), "f"(a.y), "f"(b.x), "f"(b.y));
    return r;
}
__device__ __forceinline__ float2 mul2(float2 a, float2 b) {
    float2 r;
    asm("{\n\t.reg .b64 A,B,D;\n\t"
        "mov.b64 A,{%2,%3};\n\tmov.b64 B,{%4,%5};\n\t"
        "mul.rn.f32x2 D,A,B;\n\t"
        "mov.b64 {%0,%1},D;\n\t}"
        : "=f"(r.x), "=f"(r.y)
        : "f"(a.x), "f"(a.y), "f"(b.x), "f"(b.y));
    return r;
}
__device__ __forceinline__ float2 fma2(float2 a, float2 b, float2 c) {
    float2 r;
    asm("{\n\t.reg .b64 A,B,C,D;\n\t"
        "mov.b64 A,{%2,%3};\n\tmov.b64 B,{%4,%5};\n\tmov.b64 C,{%6,%7};\n\t"
        "fma.rn.f32x2 D,A,B,C;\n\t"
        "mov.b64 {%0,%1},D;\n\t}"
        : "=f"(r.x), "=f"(r.y)
        : "f"(a.x), "f"(a.y), "f"(b.x), "f"(b.y), "f"(c.x), "f"(c.y));
    return r;
}
// Exact 2^d (d int), clamped to 0 below representable range.
__device__ __forceinline__ float exp2i(int d) {
    int e = 127 + d; e = e < 0 ? 0 : e;
    return __int_as_float(e << 23);
}
// One CTC step for pair j: lo = (v2j + v2j-1)*pb; hi = (v2j+1 + v2j + sk*v2j-1)*po
__device__ __forceinline__ float2 upd(float2 Q, float2 Qm1, float2 SK, float2 P) {
    float2 S1 = make_float2(Qm1.y, Q.x);
    return mul2(fma2(SK, Qm1, add2(Q, S1)), P);
}

__global__ __launch_bounds__(NTHREADS, 1)
void ctc_loss_kernel(const int* __restrict__ y_true,
                     const float* __restrict__ y_pred,
                     const int* __restrict__ input_len,
                     const int* __restrict__ label_len,
                     float* __restrict__ out)
{
    const int tid = threadIdx.x;
    const int g   = tid >> 7;                  // group (batch slot) 0..3
    const int i   = tid & (GT - 1);            // pair index within group
    const int b   = blockIdx.x * NG + g;       // batch element

    __shared__ float2 mbuf[NG][2][PADP + NPAIR];
    __shared__ int    ebuf[NG][2][PADP + NPAIR];
    __shared__ int    labels[NG][Lc];

    if (i < Lc) labels[g][i] = y_true[b * Lc + i];
    if (i < PADP) {
        mbuf[g][0][i] = make_float2(0.f, 0.f);
        mbuf[g][1][i] = make_float2(0.f, 0.f);
        ebuf[g][0][i] = EDEAD;
        ebuf[g][1][i] = EDEAD;
    }
    __syncthreads();

    // Static per-thread info for pairs i-3..i (odd-position class + skip).
    int    oc[4];
    float2 SK[4];
    #pragma unroll
    for (int k = 0; k < 4; ++k) {
        int pj = i - 3 + k;
        int cj = pj < 0 ? 0 : (pj > Lc - 1 ? Lc - 1 : pj);
        oc[k] = labels[g][cj];
        int cjm = cj > 0 ? cj - 1 : 0;
        float sk = (pj >= 1 && labels[g][cj] != labels[g][cjm]) ? 1.f : 0.f;
        SK[k] = make_float2(0.f, sk);
    }

    int Tb = input_len[b]; if (Tb > Tc) Tb = Tc;
    const int smax = 2 * label_len[b];
    const float* base = y_pred + (size_t)b * Tc * Cc;

    // BFP init: pair 0 alive with E=0, others dead.
    float2 A = make_float2(0.f, 0.f);
    int    E = EDEAD;
    if (i == 0) {
        A = make_float2(base[Cc - 1] + EPSV, base[oc[3]] + EPSV);
        E = 0;
    }

    // Prefetch probability scalars for the first iteration (rows 1..4).
    float bl[4], o0v, o1v[2], o2v[3], o3v[4];
    {
        const float* R = base + Cc;    // row 1 (Tb >= 500: rows 1..4 valid)
        bl[0] = R[Cc - 1]; bl[1] = R[Cc + Cc - 1];
        bl[2] = R[2 * Cc + Cc - 1]; bl[3] = R[3 * Cc + Cc - 1];
        o0v   = R[oc[0]];
        o1v[0] = R[oc[1]]; o1v[1] = R[Cc + oc[1]];
        o2v[0] = R[oc[2]]; o2v[1] = R[Cc + oc[2]]; o2v[2] = R[2 * Cc + oc[2]];
        o3v[0] = R[oc[3]]; o3v[1] = R[Cc + oc[3]];
        o3v[2] = R[2 * Cc + oc[3]]; o3v[3] = R[3 * Cc + oc[3]];
    }

    int it = 0;
    int t = 1;

    for (; t + 3 < Tb; t += 4, ++it) {
        // Pack current probabilities (+eps).
        float b0 = bl[0] + EPSV, b1 = bl[1] + EPSV;
        float b2 = bl[2] + EPSV, b3 = bl[3] + EPSV;
        float2 P1[4] = { make_float2(b0, o0v   + EPSV),
                         make_float2(b0, o1v[0] + EPSV),
                         make_float2(b0, o2v[0] + EPSV),
                         make_float2(b0, o3v[0] + EPSV) };
        float2 P2[3] = { make_float2(b1, o1v[1] + EPSV),
                         make_float2(b1, o2v[1] + EPSV),
                         make_float2(b1, o3v[1] + EPSV) };
        float2 P3[2] = { make_float2(b2, o2v[2] + EPSV),
                         make_float2(b2, o3v[2] + EPSV) };
        float2 P4    =   make_float2(b3, o3v[3] + EPSV);

        float2* mb = mbuf[g][it & 1];
        int*    eb = ebuf[g][it & 1];
        mb[PADP + i] = A;
        eb[PADP + i] = E;
        GBAR();

        // Prefetch next iteration's scalars (row base clamped in-bounds).
        {
            int r0 = t + 4; if (r0 > Tb - 4) r0 = Tb - 4;
            const float* R = base + (size_t)r0 * Cc;
            bl[0] = R[Cc - 1]; bl[1] = R[Cc + Cc - 1];
            bl[2] = R[2 * Cc + Cc - 1]; bl[3] = R[3 * Cc + Cc - 1];
            o0v   = R[oc[0]];
            o1v[0] = R[oc[1]]; o1v[1] = R[Cc + oc[1]];
            o2v[0] = R[oc[2]]; o2v[1] = R[Cc + oc[2]]; o2v[2] = R[2 * Cc + oc[2]];
            o3v[0] = R[oc[3]]; o3v[1] = R[Cc + oc[3]];
            o3v[2] = R[2 * Cc + oc[3]]; o3v[3] = R[3 * Cc + oc[3]];
        }

        // Window: pairs i-4..i-1 from shared (+ exponents), own in registers.
        float2 W[4]; int Ew[4];
        #pragma unroll
        for (int j = 0; j < 4; ++j) { W[j] = mb[i + j]; Ew[j] = eb[i + j]; }

        // Align to max exponent (exact powers of two).
        int Em = E;
        #pragma unroll
        for (int j = 0; j < 4; ++j) Em = Ew[j] > Em ? Ew[j] : Em;

        float2 V[5];
        #pragma unroll
        for (int j = 0; j < 4; ++j) {
            float f = exp2i(Ew[j] - Em);
            V[j] = mul2(W[j], make_float2(f, f));
        }
        {
            float f = exp2i(E - Em);
            V[4] = mul2(A, make_float2(f, f));
        }

        // 4-layer packed pyramid.
        float2 L1[4];
        #pragma unroll
        for (int k = 0; k < 4; ++k) L1[k] = upd(V[k + 1], V[k], SK[k], P1[k]);
        float2 L2[3];
        #pragma unroll
        for (int k = 0; k < 3; ++k) L2[k] = upd(L1[k + 1], L1[k], SK[k + 1], P2[k]);
        float2 L3[2];
        #pragma unroll
        for (int k = 0; k < 2; ++k) L3[k] = upd(L2[k + 1], L2[k], SK[k + 2], P3[k]);
        A = upd(L3[1], L3[0], SK[3], P4);

        // Renormalize by exact 2^-e (e = exponent of the pair max).
        float m = fmaxf(A.x, A.y);
        int e = ((__float_as_int(m) >> 23) & 255) - 127;
        float sfac = exp2i(-e);
        A = mul2(A, make_float2(sfac, sfac));
        E = Em + e;
    }

    // Tail: 0..3 single steps (same BFP protocol, 1-pair window).
    for (; t < Tb; ++t, ++it) {
        float2* mb = mbuf[g][it & 1];
        int*    eb = ebuf[g][it & 1];
        mb[PADP + i] = A;
        eb[PADP + i] = E;
        GBAR();
        float2 N = mb[PADP + i - 1];
        int   En = eb[PADP + i - 1];
        int   Em = E > En ? E : En;
        float fo = exp2i(E - Em), fn = exp2i(En - Em);
        float2 Vo = mul2(A, make_float2(fo, fo));
        float2 Vn = mul2(N, make_float2(fn, fn));
        float pb = base[(size_t)t * Cc + (Cc - 1)] + EPSV;
        float po = base[(size_t)t * Cc + oc[3]]    + EPSV;
        A = upd(Vo, Vn, SK[3], make_float2(pb, po));
        float m = fmaxf(A.x, A.y);
        int e = ((__float_as_int(m) >> 23) & 255) - 127;
        float sfac = exp2i(-e);
        A = mul2(A, make_float2(sfac, sfac));
        E = Em + e;
    }

    // Final readout: positions smax (pair smax/2, lo) and smax-1
    // (pair smax/2-1, hi). smax is even and >= 100.
    float2* mb = mbuf[g][it & 1];
    int*    eb = ebuf[g][it & 1];
    mb[PADP + i] = A;
    eb[PADP + i] = E;
    GBAR();
    if (i == 0) {
        int   jL = smax >> 1;
        float mL = mb[PADP + jL].x;     int EL = eb[PADP + jL];
        float mP = mb[PADP + jL - 1].y; int EP = eb[PADP + jL - 1];
        int Em = EL > EP ? EL : EP;
        float r = mL * exp2i(EL - Em) + mP * exp2i(EP - Em);
        out[b] = -LN2F * (lg2a(r) + (float)Em);
    }
}

extern "C" void kernel_launch(void* const* d_in, const int* in_sizes, int n_in,
                              void* d_out, int out_size)
{
    const int*   y_true    = (const int*)  d_in[0];  // [B,L] int32
    const float* y_pred    = (const float*)d_in[1];  // [B,T,C] float32
    const int*   input_len = (const int*)  d_in[2];  // [B] int32
    const int*   label_len = (const int*)  d_in[3];  // [B] int32
    float*       out       = (float*)d_out;          // [B,1] float32

    ctc_loss_kernel<<<Bc / NG, NTHREADS>>>(y_true, y_pred, input_len, label_len, out);
}

// round 13
// speedup vs baseline: 1.6582x; 1.6582x over previous
#include <cuda_runtime.h>
#include <math.h>

// CTC loss forward. 64 CTAs x 128 threads (4 warps, 1/SMSP). Two positions
// per thread in f32x2, block-floating-point alpha (linear float2 mantissa +
// int exponent), 4-step fused pyramid, zero MUFU in the loop.
// R13 changes vs R11 (arithmetic identical):
//  - window exchange fused into ONE float4 {m.x, m.y, bitcast(E)} per pair
//    -> 4x LDS.128 instead of 8 LDS
//  - loop order: publish STS -> barrier -> window LDS -> THEN LDG prefetch
//    (window loads no longer queue behind 13 prefetch LDGs in the LSU)
// B=64, T=1000, C=128 (blank=127), L=100, S=201.

#define Bc 64
#define Tc 1000
#define Cc 128
#define Lc 100
#define NTHREADS 128
#define NPAIR 128
#define PADP 4
#define EDEAD (-(1 << 29))

#define EPSV (1e-7f)
#define LN2F 0.6931471805599453f

__device__ __forceinline__ float lg2a(float x) {
    float y; asm("lg2.approx.f32 %0, %1;" : "=f"(y) : "f"(x)); return y;
}
__device__ __forceinline__ float2 add2(float2 a, float2 b) {
    float2 r;
    asm("{\n\t.reg .b64 A,B,D;\n\t"
        "mov.b64 A,{%2,%3};\n\tmov.b64 B,{%4,%5};\n\t"
        "add.rn.f32x2 D,A,B;\n\t"
        "mov.b64 {%0,%1},D;\n\t}"
        : "=f"(r.x), "=f"(r.y)
        : "f"(a.x), "f"(a.y), "f"(b.x), "f"(b.y));
    return r;
}
__device__ __forceinline__ float2 mul2(float2 a, float2 b) {
    float2 r;
    asm("{\n\t.reg .b64 A,B,D;\n\t"
        "mov.b64 A,{%2,%3};\n\tmov.b64 B,{%4,%5};\n\t"
        "mul.rn.f32x2 D,A,B;\n\t"
        "mov.b64 {%0,%1},D;\n\t}"
        : "=f"(r.x), "=f"(r.y)
        : "f"(a.x), "f"(a.y), "f"(b.x), "f"(b.y));
    return r;
}
__device__ __forceinline__ float2 fma2(float2 a, float2 b, float2 c) {
    float2 r;
    asm("{\n\t.reg .b64 A,B,C,D;\n\t"
        "mov.b64 A,{%2,%3};\n\tmov.b64 B,{%4,%5};\n\tmov.b64 C,{%6,%7};\n\t"
        "fma.rn.f32x2 D,A,B,C;\n\t"
        "mov.b64 {%0,%1},D;\n\t}"
        : "=f"(r.x), "=f"(r.y)
        : "f"(a.x), "f"(a.y), "f"(b.x), "f"(b.y), "f"(c.x), "f"(c.y));
    return r;
}
// Exact 2^d (d int), clamped to 0 below representable range.
__device__ __forceinline__ float exp2i(int d) {
    int e = 127 + d; e = e < 0 ? 0 : e;
    return __int_as_float(e << 23);
}
// One CTC step for pair j: lo = (v2j + v2j-1)*pb; hi = (v2j+1 + v2j + sk*v2j-1)*po
__device__ __forceinline__ float2 upd(float2 Q, float2 Qm1, float2 SK, float2 P) {
    float2 S1 = make_float2(Qm1.y, Q.x);
    return mul2(fma2(SK, Qm1, add2(Q, S1)), P);
}

__global__ __launch_bounds__(NTHREADS, 1)
void ctc_loss_kernel(const int* __restrict__ y_true,
                     const float* __restrict__ y_pred,
                     const int* __restrict__ input_len,
                     const int* __restrict__ label_len,
                     float* __restrict__ out)
{
    const int b = blockIdx.x;
    const int i = threadIdx.x;                 // pair index

    __shared__ float4 pbuf[2][PADP + NPAIR];   // {m.x, m.y, bitcast(E), pad}
    __shared__ int    labels[Lc];

    if (i < Lc) labels[i] = y_true[b * Lc + i];
    if (i < PADP) {
        float4 dead = make_float4(0.f, 0.f, __int_as_float(EDEAD), 0.f);
        pbuf[0][i] = dead;
        pbuf[1][i] = dead;
    }
    __syncthreads();

    // Static per-thread info for pairs i-3..i (odd-position class + skip).
    int    oc[4];
    float2 SK[4];
    #pragma unroll
    for (int k = 0; k < 4; ++k) {
        int pj = i - 3 + k;
        int cj = pj < 0 ? 0 : (pj > Lc - 1 ? Lc - 1 : pj);
        oc[k] = labels[cj];
        int cjm = cj > 0 ? cj - 1 : 0;
        float sk = (pj >= 1 && labels[cj] != labels[cjm]) ? 1.f : 0.f;
        SK[k] = make_float2(0.f, sk);
    }

    int Tb = input_len[b]; if (Tb > Tc) Tb = Tc;
    const int smax = 2 * label_len[b];
    const float* base = y_pred + (size_t)b * Tc * Cc;

    // BFP init: pair 0 alive with E=0, others dead.
    float2 A = make_float2(0.f, 0.f);
    int    E = EDEAD;
    if (i == 0) {
        A = make_float2(base[Cc - 1] + EPSV, base[oc[3]] + EPSV);
        E = 0;
    }

    // Prefetch probability scalars for the first iteration (rows 1..4).
    float bl[4], o0v, o1v[2], o2v[3], o3v[4];
    {
        const float* R = base + Cc;    // row 1 (Tb >= 500: rows 1..4 valid)
        bl[0] = R[Cc - 1]; bl[1] = R[Cc + Cc - 1];
        bl[2] = R[2 * Cc + Cc - 1]; bl[3] = R[3 * Cc + Cc - 1];
        o0v   = R[oc[0]];
        o1v[0] = R[oc[1]]; o1v[1] = R[Cc + oc[1]];
        o2v[0] = R[oc[2]]; o2v[1] = R[Cc + oc[2]]; o2v[2] = R[2 * Cc + oc[2]];
        o3v[0] = R[oc[3]]; o3v[1] = R[Cc + oc[3]];
        o3v[2] = R[2 * Cc + oc[3]]; o3v[3] = R[3 * Cc + oc[3]];
    }

    int it = 0;
    int t = 1;

    for (; t + 3 < Tb; t += 4, ++it) {
        // Pack current probabilities (+eps) from last iteration's prefetch.
        float b0 = bl[0] + EPSV, b1 = bl[1] + EPSV;
        float b2 = bl[2] + EPSV, b3 = bl[3] + EPSV;
        float2 P1[4] = { make_float2(b0, o0v   + EPSV),
                         make_float2(b0, o1v[0] + EPSV),
                         make_float2(b0, o2v[0] + EPSV),
                         make_float2(b0, o3v[0] + EPSV) };
        float2 P2[3] = { make_float2(b1, o1v[1] + EPSV),
                         make_float2(b1, o2v[1] + EPSV),
                         make_float2(b1, o3v[1] + EPSV) };
        float2 P3[2] = { make_float2(b2, o2v[2] + EPSV),
                         make_float2(b2, o3v[2] + EPSV) };
        float2 P4    =   make_float2(b3, o3v[3] + EPSV);

        // Publish, barrier, then read window FIRST (before any LDG issue).
        float4* pb = pbuf[it & 1];
        pb[PADP + i] = make_float4(A.x, A.y, __int_as_float(E), 0.f);
        __syncthreads();

        float4 W4[4];
        #pragma unroll
        for (int j = 0; j < 4; ++j) W4[j] = pb[i + j];   // pair (i-4+j)

        // Prefetch next iteration's scalars AFTER the window loads.
        {
            int r0 = t + 4; if (r0 > Tb - 4) r0 = Tb - 4;
            const float* R = base + (size_t)r0 * Cc;
            bl[0] = R[Cc - 1]; bl[1] = R[Cc + Cc - 1];
            bl[2] = R[2 * Cc + Cc - 1]; bl[3] = R[3 * Cc + Cc - 1];
            o0v   = R[oc[0]];
            o1v[0] = R[oc[1]]; o1v[1] = R[Cc + oc[1]];
            o2v[0] = R[oc[2]]; o2v[1] = R[Cc + oc[2]]; o2v[2] = R[2 * Cc + oc[2]];
            o3v[0] = R[oc[3]]; o3v[1] = R[Cc + oc[3]];
            o3v[2] = R[2 * Cc + oc[3]]; o3v[3] = R[3 * Cc + oc[3]];
        }

        // Align to max exponent (exact powers of two).
        int Ew0 = __float_as_int(W4[0].z), Ew1 = __float_as_int(W4[1].z);
        int Ew2 = __float_as_int(W4[2].z), Ew3 = __float_as_int(W4[3].z);
        int Em = E;
        Em = Ew0 > Em ? Ew0 : Em;
        Em = Ew1 > Em ? Ew1 : Em;
        Em = Ew2 > Em ? Ew2 : Em;
        Em = Ew3 > Em ? Ew3 : Em;

        float2 V[5];
        {
            float f0 = exp2i(Ew0 - Em);
            float f1 = exp2i(Ew1 - Em);
            float f2 = exp2i(Ew2 - Em);
            float f3 = exp2i(Ew3 - Em);
            float f4 = exp2i(E   - Em);
            V[0] = mul2(make_float2(W4[0].x, W4[0].y), make_float2(f0, f0));
            V[1] = mul2(make_float2(W4[1].x, W4[1].y), make_float2(f1, f1));
            V[2] = mul2(make_float2(W4[2].x, W4[2].y), make_float2(f2, f2));
            V[3] = mul2(make_float2(W4[3].x, W4[3].y), make_float2(f3, f3));
            V[4] = mul2(A, make_float2(f4, f4));
        }

        // 4-layer packed pyramid.
        float2 L1[4];
        #pragma unroll
        for (int k = 0; k < 4; ++k) L1[k] = upd(V[k + 1], V[k], SK[k], P1[k]);
        float2 L2[3];
        #pragma unroll
        for (int k = 0; k < 3; ++k) L2[k] = upd(L1[k + 1], L1[k], SK[k + 1], P2[k]);
        float2 L3[2];
        #pragma unroll
        for (int k = 0; k < 2; ++k) L3[k] = upd(L2[k + 1], L2[k], SK[k + 2], P3[k]);
        A = upd(L3[1], L3[0], SK[3], P4);

        // Renormalize by exact 2^-e (e = exponent of the pair max).
        float m = fmaxf(A.x, A.y);
        int e = ((__float_as_int(m) >> 23) & 255) - 127;
        float sfac = exp2i(-e);
        A = mul2(A, make_float2(sfac, sfac));
        E = Em + e;
    }

    // Tail: 0..3 single steps (same BFP protocol, 1-pair window).
    for (; t < Tb; ++t, ++it) {
        float4* pb = pbuf[it & 1];
        pb[PADP + i] = make_float4(A.x, A.y, __int_as_float(E), 0.f);
        __syncthreads();
        float4 N4 = pb[PADP + i - 1];
        int   En = __float_as_int(N4.z);
        int   Em = E > En ? E : En;
        float fo = exp2i(E - Em), fn = exp2i(En - Em);
        float2 Vo = mul2(A, make_float2(fo, fo));
        float2 Vn = mul2(make_float2(N4.x, N4.y), make_float2(fn, fn));
        float pbv = base[(size_t)t * Cc + (Cc - 1)] + EPSV;
        float pov = base[(size_t)t * Cc + oc[3]]    + EPSV;
        A = upd(Vo, Vn, SK[3], make_float2(pbv, pov));
        float m = fmaxf(A.x, A.y);
        int e = ((__float_as_int(m) >> 23) & 255) - 127;
        float sfac = exp2i(-e);
        A = mul2(A, make_float2(sfac, sfac));
        E = Em + e;
    }

    // Final readout: positions smax (pair smax/2, lo) and smax-1
    // (pair smax/2-1, hi). smax is even and >= 100.
    float4* pb = pbuf[it & 1];
    pb[PADP + i] = make_float4(A.x, A.y, __int_as_float(E), 0.f);
    __syncthreads();
    if (i == 0) {
        int    jL = smax >> 1;
        float4 QL = pb[PADP + jL];
        float4 QP = pb[PADP + jL - 1];
        int EL = __float_as_int(QL.z);
        int EP = __float_as_int(QP.z);
        int Em = EL > EP ? EL : EP;
        float r = QL.x * exp2i(EL - Em) + QP.y * exp2i(EP - Em);
        out[b] = -LN2F * (lg2a(r) + (float)Em);
    }
}

extern "C" void kernel_launch(void* const* d_in, const int* in_sizes, int n_in,
                              void* d_out, int out_size)
{
    const int*   y_true    = (const int*)  d_in[0];  // [B,L] int32
    const float* y_pred    = (const float*)d_in[1];  // [B,T,C] float32
    const int*   input_len = (const int*)  d_in[2];  // [B] int32
    const int*   label_len = (const int*)  d_in[3];  // [B] int32
    float*       out       = (float*)d_out;          // [B,1] float32

    ctc_loss_kernel<<<Bc, NTHREADS>>>(y_true, y_pred, input_len, label_len, out);
}